// round 15
// baseline (speedup 1.0000x reference)
#include <cuda_runtime.h>
#include <cuda_bf16.h>
#include <cstdint>

// ---------------- problem constants ----------------
#define NN      10000
#define EE      320000
#define D_IN    128
#define HH      128
#define LL      3
#define D_CAT   256
#define WH      256
#define D_OUT   128
#define LN_EPS  1e-5f
#define SLOPE   0.1f
#define CAP     128      // per-node edge bucket capacity (max degree ~65 for Poisson(32))

// ---------------- scratch ----------------
__device__ float g_HID[NN * 512];
__device__ float g_Z  [NN * D_CAT];
__device__ float g_T1 [NN * WH];
__device__ float g_T2 [NN * WH];
__device__ int   g_is_i64;
__device__ int   g_count[NN];
__device__ int2  g_srcea[NN * CAP];   // bucketed (src, ea bits) per dst

// ---------------- detect dtype + zero counters (merged) ----------------
__global__ void detect_zero_kernel(const unsigned int* __restrict__ w) {
    int i = blockIdx.x * blockDim.x + threadIdx.x;
    if (i < NN) g_count[i] = 0;
    if (blockIdx.x == 0) {
        __shared__ int bad;
        if (threadIdx.x == 0) bad = 0;
        __syncthreads();
        if (w[2 * threadIdx.x + 1] != 0u) atomicExch(&bad, 1);
        __syncthreads();
        if (threadIdx.x == 0) g_is_i64 = (bad == 0) ? 1 : 0;
    }
}

// ---------------- bucket scatter ----------------
__global__ void scatter_kernel(const void* __restrict__ ei,
                               const float* __restrict__ ea) {
    int e = blockIdx.x * blockDim.x + threadIdx.x;
    if (e >= EE) return;
    int src, dst;
    if (g_is_i64) {
        src = (int)((const long long*)ei)[e];
        dst = (int)((const long long*)ei)[EE + e];
    } else {
        src = ((const int*)ei)[e];
        dst = ((const int*)ei)[EE + e];
    }
    int pos = atomicAdd(&g_count[dst], 1);
    if (pos < CAP) g_srcea[dst * CAP + pos] = make_int2(src, __float_as_int(__ldg(ea + e)));
}

// ---------------- aggregation: 1 warp per node, 8 dims/thread (both halves) ----------------
// lane t: dims [4t,4t+4) of x-half (stride 128) AND [128+4t,128+4t+4) of h-half (stride 512).
__global__ void agg_z_kernel(const float* __restrict__ x,
                             const float* __restrict__ eWl,
                             const float* __restrict__ eBl,
                             int hid_off) {
    int node = blockIdx.x * 8 + (threadIdx.x >> 5);   // grid 1250, 8 nodes/block
    int lane = threadIdx.x & 31;
    int d = lane * 4;

    float4 wx = *(const float4*)(eWl + d);
    float4 bx = *(const float4*)(eBl + d);
    float4 wh = *(const float4*)(eWl + 128 + d);
    float4 bh = *(const float4*)(eBl + 128 + d);

    const float* xb = x + d;                        // stride 128 (compile-time)
    const float* hb = g_HID + hid_off + d;          // stride 512 (compile-time)

    float4 accx = *(const float4*)(xb + (size_t)node * 128);
    float4 acch = *(const float4*)(hb + (size_t)node * 512);

    int i   = node * CAP;
    int end = i + min(g_count[node], CAP);

    auto body = [&](int2 se) {
        float a = __int_as_float(se.y);
        float4 vx = *(const float4*)(xb + se.x * 128);
        float4 vh = *(const float4*)(hb + se.x * 512);
        accx.x += fmaxf(vx.x + fmaf(a, wx.x, bx.x), 0.f);
        accx.y += fmaxf(vx.y + fmaf(a, wx.y, bx.y), 0.f);
        accx.z += fmaxf(vx.z + fmaf(a, wx.z, bx.z), 0.f);
        accx.w += fmaxf(vx.w + fmaf(a, wx.w, bx.w), 0.f);
        acch.x += fmaxf(vh.x + fmaf(a, wh.x, bh.x), 0.f);
        acch.y += fmaxf(vh.y + fmaf(a, wh.y, bh.y), 0.f);
        acch.z += fmaxf(vh.z + fmaf(a, wh.z, bh.z), 0.f);
        acch.w += fmaxf(vh.w + fmaf(a, wh.w, bh.w), 0.f);
    };
    for (; i + 2 <= end; i += 2) {
        int2 s0 = g_srcea[i], s1 = g_srcea[i + 1];
        body(s0); body(s1);
    }
    for (; i < end; i++) body(g_srcea[i]);

    float* zp = g_Z + (size_t)node * D_CAT + d;
    *(float4*)(zp)       = accx;
    *(float4*)(zp + 128) = acch;
}

// ---------------- LayerNorm + LeakyReLU: one warp per row, shuffle-only ----------------
__global__ void ln_leaky_kernel(float* __restrict__ T,
                                const float* __restrict__ g,
                                const float* __restrict__ b) {
    int warp = threadIdx.x >> 5;
    int lane = threadIdx.x & 31;
    int row  = blockIdx.x * 8 + warp;          // grid = 1250, 8 rows/block
    float* rp = T + (size_t)row * WH + lane * 8;

    float4 v0 = *(const float4*)(rp);
    float4 v1 = *(const float4*)(rp + 4);

    float s  = v0.x + v0.y + v0.z + v0.w + v1.x + v1.y + v1.z + v1.w;
    float s2 = v0.x * v0.x + v0.y * v0.y + v0.z * v0.z + v0.w * v0.w
             + v1.x * v1.x + v1.y * v1.y + v1.z * v1.z + v1.w * v1.w;
    #pragma unroll
    for (int off = 16; off > 0; off >>= 1) {
        s  += __shfl_xor_sync(0xffffffffu, s,  off);
        s2 += __shfl_xor_sync(0xffffffffu, s2, off);
    }
    float mu   = s * (1.0f / WH);
    float var  = s2 * (1.0f / WH) - mu * mu;
    float rstd = rsqrtf(var + LN_EPS);

    float4 g0 = *(const float4*)(g + lane * 8);
    float4 g1 = *(const float4*)(g + lane * 8 + 4);
    float4 b0 = *(const float4*)(b + lane * 8);
    float4 b1 = *(const float4*)(b + lane * 8 + 4);

    float y;
    y = (v0.x - mu) * rstd * g0.x + b0.x; v0.x = (y > 0.f) ? y : SLOPE * y;
    y = (v0.y - mu) * rstd * g0.y + b0.y; v0.y = (y > 0.f) ? y : SLOPE * y;
    y = (v0.z - mu) * rstd * g0.z + b0.z; v0.z = (y > 0.f) ? y : SLOPE * y;
    y = (v0.w - mu) * rstd * g0.w + b0.w; v0.w = (y > 0.f) ? y : SLOPE * y;
    y = (v1.x - mu) * rstd * g1.x + b1.x; v1.x = (y > 0.f) ? y : SLOPE * y;
    y = (v1.y - mu) * rstd * g1.y + b1.y; v1.y = (y > 0.f) ? y : SLOPE * y;
    y = (v1.z - mu) * rstd * g1.z + b1.z; v1.z = (y > 0.f) ? y : SLOPE * y;
    y = (v1.w - mu) * rstd * g1.w + b1.w; v1.w = (y > 0.f) ? y : SLOPE * y;

    *(float4*)(rp)     = v0;
    *(float4*)(rp + 4) = v1;
}

// ================= bf16x3 tensor-core GEMM (champion kernel, unchanged) =================
__device__ __forceinline__ void ldsm4(unsigned* r, const __nv_bfloat16* p) {
    unsigned a = (unsigned)__cvta_generic_to_shared(p);
    asm volatile("ldmatrix.sync.aligned.m8n8.x4.shared.b16 {%0,%1,%2,%3}, [%4];"
                 : "=r"(r[0]), "=r"(r[1]), "=r"(r[2]), "=r"(r[3]) : "r"(a));
}
__device__ __forceinline__ void ldsm4t(unsigned* r, const __nv_bfloat16* p) {
    unsigned a = (unsigned)__cvta_generic_to_shared(p);
    asm volatile("ldmatrix.sync.aligned.m8n8.x4.trans.shared.b16 {%0,%1,%2,%3}, [%4];"
                 : "=r"(r[0]), "=r"(r[1]), "=r"(r[2]), "=r"(r[3]) : "r"(a));
}
__device__ __forceinline__ void mma_bf16(float* c, const unsigned* a, const unsigned* b) {
    asm volatile("mma.sync.aligned.m16n8k16.row.col.f32.bf16.bf16.f32 "
                 "{%0,%1,%2,%3}, {%4,%5,%6,%7}, {%8,%9}, {%0,%1,%2,%3};"
                 : "+f"(c[0]), "+f"(c[1]), "+f"(c[2]), "+f"(c[3])
                 : "r"(a[0]), "r"(a[1]), "r"(a[2]), "r"(a[3]), "r"(b[0]), "r"(b[1]));
}
__device__ __forceinline__ void split_bf16(float v, unsigned short& h, unsigned short& l) {
    __nv_bfloat16 hb = __float2bfloat16_rn(v);
    float res = v - __bfloat162float(hb);
    h = __bfloat16_as_ushort(hb);
    l = __bfloat16_as_ushort(__float2bfloat16_rn(res));
}

template <int BN, bool LEAKY>
__global__ __launch_bounds__(256, 2)
void bf16x3_gemm_kernel(int M, int K,
                        const float* __restrict__ A, int lda,
                        const float* __restrict__ B, int ldb,
                        const float* __restrict__ bias,
                        float* __restrict__ C, int ldc) {
    constexpr int NB8     = BN / 8;
    constexpr int WARPS_N = BN / 32;
    constexpr int WARPS_M = 8 / WARPS_N;
    constexpr int MT      = (128 / WARPS_M) / 16;
    constexpr int B_ITERS = BN / 64;
    constexpr int F4_ROW  = BN / 4;

    __shared__ __align__(16) __nv_bfloat16 Ah[128 * 16], Al[128 * 16];
    __shared__ __align__(16) __nv_bfloat16 Bh[16 * BN],  Bl[16 * BN];

    const int tid   = threadIdx.x;
    const int w     = tid >> 5;
    const int lane  = tid & 31;
    const int g     = lane >> 2;
    const int q     = lane & 3;
    const int warpN = (w % WARPS_N) * 32;
    const int warpM = (w / WARPS_N) * (MT * 16);
    const int brow  = blockIdx.x * 128;
    const int bcol  = blockIdx.y * BN;

    float acc[MT][4][4];
    #pragma unroll
    for (int mt = 0; mt < MT; mt++)
        #pragma unroll
        for (int nt = 0; nt < 4; nt++)
            #pragma unroll
            for (int i = 0; i < 4; i++) acc[mt][nt][i] = 0.f;

    float4 pa[2], pb[B_ITERS];

    auto load_tile = [&](int k0) {
        #pragma unroll
        for (int i = 0; i < 2; i++) {
            int idx = tid + i * 256;
            int r   = idx >> 2;
            int kq  = (idx & 3) * 4;
            pa[i] = (brow + r < M)
                  ? *(const float4*)(A + (size_t)(brow + r) * lda + k0 + kq)
                  : make_float4(0.f, 0.f, 0.f, 0.f);
        }
        #pragma unroll
        for (int i = 0; i < B_ITERS; i++) {
            int idx = tid + i * 256;
            int k   = idx / F4_ROW;
            int n4  = (idx % F4_ROW) * 4;
            pb[i] = *(const float4*)(B + (size_t)(k0 + k) * ldb + bcol + n4);
        }
    };
    auto store_tile = [&]() {
        #pragma unroll
        for (int i = 0; i < 2; i++) {
            int idx = tid + i * 256;
            int r   = idx >> 2;
            int kq  = (idx & 3) * 4;
            float vv[4] = {pa[i].x, pa[i].y, pa[i].z, pa[i].w};
            unsigned short h[4], l[4];
            #pragma unroll
            for (int j = 0; j < 4; j++) split_bf16(vv[j], h[j], l[j]);
            int ci = (r * 2 + ((kq >> 3) ^ ((r >> 2) & 1))) * 8 + (kq & 4);
            *(uint2*)&Ah[ci] = make_uint2((unsigned)h[0] | ((unsigned)h[1] << 16),
                                          (unsigned)h[2] | ((unsigned)h[3] << 16));
            *(uint2*)&Al[ci] = make_uint2((unsigned)l[0] | ((unsigned)l[1] << 16),
                                          (unsigned)l[2] | ((unsigned)l[3] << 16));
        }
        #pragma unroll
        for (int i = 0; i < B_ITERS; i++) {
            int idx = tid + i * 256;
            int k   = idx / F4_ROW;
            int n4  = (idx % F4_ROW) * 4;
            float vv[4] = {pb[i].x, pb[i].y, pb[i].z, pb[i].w};
            unsigned short h[4], l[4];
            #pragma unroll
            for (int j = 0; j < 4; j++) split_bf16(vv[j], h[j], l[j]);
            int ci = (k * NB8 + ((n4 >> 3) ^ (k & 7))) * 8 + (n4 & 4);
            *(uint2*)&Bh[ci] = make_uint2((unsigned)h[0] | ((unsigned)h[1] << 16),
                                          (unsigned)h[2] | ((unsigned)h[3] << 16));
            *(uint2*)&Bl[ci] = make_uint2((unsigned)l[0] | ((unsigned)l[1] << 16),
                                          (unsigned)l[2] | ((unsigned)l[3] << 16));
        }
    };

    load_tile(0);
    store_tile();
    __syncthreads();

    for (int k0 = 0; k0 < K; k0 += 16) {
        bool more = (k0 + 16) < K;
        if (more) load_tile(k0 + 16);

        unsigned bhf[4][2], blf[4][2];
        #pragma unroll
        for (int j = 0; j < 2; j++) {
            int k  = lane & 15;
            int n8 = ((warpN + j * 16) >> 3) + (lane >> 4);
            int ch = k * NB8 + (n8 ^ (k & 7));
            unsigned r4[4];
            ldsm4t(r4, &Bh[ch * 8]);
            bhf[2 * j][0] = r4[0]; bhf[2 * j][1] = r4[1];
            bhf[2 * j + 1][0] = r4[2]; bhf[2 * j + 1][1] = r4[3];
            ldsm4t(r4, &Bl[ch * 8]);
            blf[2 * j][0] = r4[0]; blf[2 * j][1] = r4[1];
            blf[2 * j + 1][0] = r4[2]; blf[2 * j + 1][1] = r4[3];
        }
        #pragma unroll
        for (int mt = 0; mt < MT; mt++) {
            int r  = warpM + mt * 16 + (lane & 15);
            int kh = lane >> 4;
            int ch = r * 2 + (kh ^ ((r >> 2) & 1));
            unsigned ah[4], al[4];
            ldsm4(ah, &Ah[ch * 8]);
            ldsm4(al, &Al[ch * 8]);
            #pragma unroll
            for (int nt = 0; nt < 4; nt++) {
                mma_bf16(acc[mt][nt], ah, bhf[nt]);
                mma_bf16(acc[mt][nt], ah, blf[nt]);
                mma_bf16(acc[mt][nt], al, bhf[nt]);
            }
        }
        __syncthreads();
        if (more) {
            store_tile();
            __syncthreads();
        }
    }

    #pragma unroll
    for (int nt = 0; nt < 4; nt++) {
        int gc = bcol + warpN + nt * 8 + 2 * q;
        float bx = bias[gc], by = bias[gc + 1];
        #pragma unroll
        for (int mt = 0; mt < MT; mt++) {
            int gr0 = brow + warpM + mt * 16 + g;
            float v0 = acc[mt][nt][0] + bx;
            float v1 = acc[mt][nt][1] + by;
            float v2 = acc[mt][nt][2] + bx;
            float v3 = acc[mt][nt][3] + by;
            if (LEAKY) {
                v0 = (v0 > 0.f) ? v0 : SLOPE * v0;
                v1 = (v1 > 0.f) ? v1 : SLOPE * v1;
                v2 = (v2 > 0.f) ? v2 : SLOPE * v2;
                v3 = (v3 > 0.f) ? v3 : SLOPE * v3;
            }
            if (gr0 < M)     *(float2*)(C + (size_t)gr0 * ldc + gc)       = make_float2(v0, v1);
            if (gr0 + 8 < M) *(float2*)(C + (size_t)(gr0 + 8) * ldc + gc) = make_float2(v2, v3);
        }
    }
}

// ---------------- launcher ----------------
extern "C" void kernel_launch(void* const* d_in, const int* in_sizes, int n_in,
                              void* d_out, int out_size) {
    const float* x      = (const float*)d_in[0];
    const void*  ei     = d_in[1];
    const float* ea     = (const float*)d_in[2];
    const float* in_W   = (const float*)d_in[3];
    const float* in_b   = (const float*)d_in[4];
    const float* eW     = (const float*)d_in[5];
    const float* eB     = (const float*)d_in[6];
    const float* W1     = (const float*)d_in[7];
    const float* b1     = (const float*)d_in[8];
    const float* ln_g   = (const float*)d_in[9];
    const float* ln_b   = (const float*)d_in[10];
    const float* W2     = (const float*)d_in[11];
    const float* b2     = (const float*)d_in[12];
    const float* W3     = (const float*)d_in[13];
    const float* b3     = (const float*)d_in[14];
    const float* out_W  = (const float*)d_in[15];
    const float* out_b  = (const float*)d_in[16];
    float* out = (float*)d_out;

    float* HID; cudaGetSymbolAddress((void**)&HID, g_HID);
    float* Z;   cudaGetSymbolAddress((void**)&Z,   g_Z);
    float* T1;  cudaGetSymbolAddress((void**)&T1,  g_T1);
    float* T2;  cudaGetSymbolAddress((void**)&T2,  g_T2);

    // 0) dtype detect + zero + bucket scatter
    detect_zero_kernel<<<(NN + 1023) / 1024, 1024>>>((const unsigned int*)ei);
    scatter_kernel<<<(EE + 255) / 256, 256>>>(ei, ea);

    // 1) h0 = x @ in_W + in_b  -> HID[:, 0:128]
    bf16x3_gemm_kernel<64, false><<<dim3(79, 2), 256>>>(
        NN, 128, x, D_IN, in_W, HH, in_b, HID, 512);

    // 2) GINE layers
    for (int l = 0; l < LL; l++) {
        int hid_off = l * HH;
        const float* eWl = eW + l * D_CAT;
        const float* eBl = eB + l * D_CAT;
        const float* W1l = W1 + (size_t)l * D_CAT * WH;
        const float* W2l = W2 + (size_t)l * WH * WH;
        const float* W3l = W3 + (size_t)l * WH * HH;

        agg_z_kernel<<<NN / 8, 256>>>(x, eWl, eBl, hid_off);
        bf16x3_gemm_kernel<128, false><<<dim3(79, 2), 256>>>(
            NN, D_CAT, Z, D_CAT, W1l, WH, b1 + l * WH, T1, WH);
        ln_leaky_kernel<<<NN / 8, 256>>>(T1, ln_g + l * WH, ln_b + l * WH);
        bf16x3_gemm_kernel<128, true><<<dim3(79, 2), 256>>>(
            NN, WH, T1, WH, W2l, WH, b2 + l * WH, T2, WH);
        bf16x3_gemm_kernel<64, false><<<dim3(79, 2), 256>>>(
            NN, WH, T2, WH, W3l, HH, b3 + l * HH, HID + (l + 1) * HH, 512);
    }

    // 3) out = HID @ out_W + out_b
    bf16x3_gemm_kernel<64, false><<<dim3(79, 2), 256>>>(
        NN, 512, HID, 512, out_W, D_OUT, out_b, out, D_OUT);

    (void)in_sizes; (void)n_in; (void)out_size;
}

// round 16
// speedup vs baseline: 1.0551x; 1.0551x over previous
#include <cuda_runtime.h>
#include <cuda_bf16.h>
#include <cstdint>

// ---------------- problem constants ----------------
#define NN      10000
#define EE      320000
#define D_IN    128
#define HH      128
#define LL      3
#define D_CAT   256
#define WH      256
#define D_OUT   128
#define LN_EPS  1e-5f
#define SLOPE   0.1f
#define CAP     128      // per-node edge bucket capacity (max degree ~65 for Poisson(32))

// ---------------- scratch ----------------
__device__ float g_HID[NN * 512];
__device__ float g_Z  [NN * D_CAT];
__device__ float g_T1 [NN * WH];
__device__ float g_T2 [NN * WH];
__device__ int   g_is_i64;
__device__ int   g_count[NN];
__device__ int2  g_srcea[NN * CAP];   // bucketed (src, ea bits) per dst

// ---------------- detect dtype + zero counters (merged) ----------------
__global__ void detect_zero_kernel(const unsigned int* __restrict__ w) {
    int i = blockIdx.x * blockDim.x + threadIdx.x;
    if (i < NN) g_count[i] = 0;
    if (blockIdx.x == 0) {
        __shared__ int bad;
        if (threadIdx.x == 0) bad = 0;
        __syncthreads();
        if (w[2 * threadIdx.x + 1] != 0u) atomicExch(&bad, 1);
        __syncthreads();
        if (threadIdx.x == 0) g_is_i64 = (bad == 0) ? 1 : 0;
    }
}

// ---------------- bucket scatter ----------------
__global__ void scatter_kernel(const void* __restrict__ ei,
                               const float* __restrict__ ea) {
    int e = blockIdx.x * blockDim.x + threadIdx.x;
    if (e >= EE) return;
    int src, dst;
    if (g_is_i64) {
        src = (int)((const long long*)ei)[e];
        dst = (int)((const long long*)ei)[EE + e];
    } else {
        src = ((const int*)ei)[e];
        dst = ((const int*)ei)[EE + e];
    }
    int pos = atomicAdd(&g_count[dst], 1);
    if (pos < CAP) g_srcea[dst * CAP + pos] = make_int2(src, __float_as_int(__ldg(ea + e)));
}

// ---------------- aggregation (R14 champion: fp32 gathers, 4 nodes/block) ----------------
__global__ void agg_z_kernel(const float* __restrict__ x,
                             const float* __restrict__ eWl,
                             const float* __restrict__ eBl,
                             int hid_off) {
    int node = blockIdx.x * 4 + (threadIdx.x >> 6);
    if (node >= NN) return;
    int lane = threadIdx.x & 63;
    int d = lane * 4;

    float4 w  = *(const float4*)(eWl + d);
    float4 bb = *(const float4*)(eBl + d);

    float4 acc;
    if (d < 128) acc = *(const float4*)(x + (size_t)node * D_IN + d);
    else         acc = *(const float4*)(g_HID + (size_t)node * 512 + hid_off + (d - 128));

    const float* gbase = (d < 128) ? (x + d) : (g_HID + hid_off + (d - 128));
    const size_t gstr  = (d < 128) ? D_IN : 512;

    int i   = node * CAP;
    int end = i + min(g_count[node], CAP);

    auto body = [&](int2 se) {
        float4 v = *(const float4*)(gbase + (size_t)se.x * gstr);
        float a = __int_as_float(se.y);
        acc.x += fmaxf(v.x + fmaf(a, w.x, bb.x), 0.f);
        acc.y += fmaxf(v.y + fmaf(a, w.y, bb.y), 0.f);
        acc.z += fmaxf(v.z + fmaf(a, w.z, bb.z), 0.f);
        acc.w += fmaxf(v.w + fmaf(a, w.w, bb.w), 0.f);
    };
    for (; i + 4 <= end; i += 4) {
        int2 s0 = g_srcea[i], s1 = g_srcea[i + 1], s2 = g_srcea[i + 2], s3 = g_srcea[i + 3];
        body(s0); body(s1); body(s2); body(s3);
    }
    for (; i < end; i++) body(g_srcea[i]);

    *(float4*)(g_Z + (size_t)node * D_CAT + d) = acc;
}

// ---------------- LayerNorm + LeakyReLU: one warp per row, shuffle-only ----------------
__global__ void ln_leaky_kernel(float* __restrict__ T,
                                const float* __restrict__ g,
                                const float* __restrict__ b) {
    int warp = threadIdx.x >> 5;
    int lane = threadIdx.x & 31;
    int row  = blockIdx.x * 8 + warp;          // grid = 1250, 8 rows/block
    float* rp = T + (size_t)row * WH + lane * 8;

    float4 v0 = *(const float4*)(rp);
    float4 v1 = *(const float4*)(rp + 4);

    float s  = v0.x + v0.y + v0.z + v0.w + v1.x + v1.y + v1.z + v1.w;
    float s2 = v0.x * v0.x + v0.y * v0.y + v0.z * v0.z + v0.w * v0.w
             + v1.x * v1.x + v1.y * v1.y + v1.z * v1.z + v1.w * v1.w;
    #pragma unroll
    for (int off = 16; off > 0; off >>= 1) {
        s  += __shfl_xor_sync(0xffffffffu, s,  off);
        s2 += __shfl_xor_sync(0xffffffffu, s2, off);
    }
    float mu   = s * (1.0f / WH);
    float var  = s2 * (1.0f / WH) - mu * mu;
    float rstd = rsqrtf(var + LN_EPS);

    float4 g0 = *(const float4*)(g + lane * 8);
    float4 g1 = *(const float4*)(g + lane * 8 + 4);
    float4 b0 = *(const float4*)(b + lane * 8);
    float4 b1 = *(const float4*)(b + lane * 8 + 4);

    float y;
    y = (v0.x - mu) * rstd * g0.x + b0.x; v0.x = (y > 0.f) ? y : SLOPE * y;
    y = (v0.y - mu) * rstd * g0.y + b0.y; v0.y = (y > 0.f) ? y : SLOPE * y;
    y = (v0.z - mu) * rstd * g0.z + b0.z; v0.z = (y > 0.f) ? y : SLOPE * y;
    y = (v0.w - mu) * rstd * g0.w + b0.w; v0.w = (y > 0.f) ? y : SLOPE * y;
    y = (v1.x - mu) * rstd * g1.x + b1.x; v1.x = (y > 0.f) ? y : SLOPE * y;
    y = (v1.y - mu) * rstd * g1.y + b1.y; v1.y = (y > 0.f) ? y : SLOPE * y;
    y = (v1.z - mu) * rstd * g1.z + b1.z; v1.z = (y > 0.f) ? y : SLOPE * y;
    y = (v1.w - mu) * rstd * g1.w + b1.w; v1.w = (y > 0.f) ? y : SLOPE * y;

    *(float4*)(rp)     = v0;
    *(float4*)(rp + 4) = v1;
}

// ================= bf16x3 tensor-core GEMM — double-buffered smem, 1 sync/iter =================
__device__ __forceinline__ void ldsm4(unsigned* r, const __nv_bfloat16* p) {
    unsigned a = (unsigned)__cvta_generic_to_shared(p);
    asm volatile("ldmatrix.sync.aligned.m8n8.x4.shared.b16 {%0,%1,%2,%3}, [%4];"
                 : "=r"(r[0]), "=r"(r[1]), "=r"(r[2]), "=r"(r[3]) : "r"(a));
}
__device__ __forceinline__ void ldsm4t(unsigned* r, const __nv_bfloat16* p) {
    unsigned a = (unsigned)__cvta_generic_to_shared(p);
    asm volatile("ldmatrix.sync.aligned.m8n8.x4.trans.shared.b16 {%0,%1,%2,%3}, [%4];"
                 : "=r"(r[0]), "=r"(r[1]), "=r"(r[2]), "=r"(r[3]) : "r"(a));
}
__device__ __forceinline__ void mma_bf16(float* c, const unsigned* a, const unsigned* b) {
    asm volatile("mma.sync.aligned.m16n8k16.row.col.f32.bf16.bf16.f32 "
                 "{%0,%1,%2,%3}, {%4,%5,%6,%7}, {%8,%9}, {%0,%1,%2,%3};"
                 : "+f"(c[0]), "+f"(c[1]), "+f"(c[2]), "+f"(c[3])
                 : "r"(a[0]), "r"(a[1]), "r"(a[2]), "r"(a[3]), "r"(b[0]), "r"(b[1]));
}
__device__ __forceinline__ void split_bf16(float v, unsigned short& h, unsigned short& l) {
    __nv_bfloat16 hb = __float2bfloat16_rn(v);
    float res = v - __bfloat162float(hb);
    h = __bfloat16_as_ushort(hb);
    l = __bfloat16_as_ushort(__float2bfloat16_rn(res));
}

template <int BN, bool LEAKY>
__global__ __launch_bounds__(256, 2)
void bf16x3_gemm_kernel(int M, int K,
                        const float* __restrict__ A, int lda,
                        const float* __restrict__ B, int ldb,
                        const float* __restrict__ bias,
                        float* __restrict__ C, int ldc) {
    constexpr int NB8     = BN / 8;
    constexpr int WARPS_N = BN / 32;
    constexpr int WARPS_M = 8 / WARPS_N;
    constexpr int MT      = (128 / WARPS_M) / 16;
    constexpr int B_ITERS = BN / 64;
    constexpr int F4_ROW  = BN / 4;

    __shared__ __align__(16) __nv_bfloat16 Ah[2][128 * 16], Al[2][128 * 16];
    __shared__ __align__(16) __nv_bfloat16 Bh[2][16 * BN],  Bl[2][16 * BN];

    const int tid   = threadIdx.x;
    const int w     = tid >> 5;
    const int lane  = tid & 31;
    const int g     = lane >> 2;
    const int q     = lane & 3;
    const int warpN = (w % WARPS_N) * 32;
    const int warpM = (w / WARPS_N) * (MT * 16);
    const int brow  = blockIdx.x * 128;
    const int bcol  = blockIdx.y * BN;

    float acc[MT][4][4];
    #pragma unroll
    for (int mt = 0; mt < MT; mt++)
        #pragma unroll
        for (int nt = 0; nt < 4; nt++)
            #pragma unroll
            for (int i = 0; i < 4; i++) acc[mt][nt][i] = 0.f;

    float4 pa[2], pb[B_ITERS];

    auto load_tile = [&](int k0) {
        #pragma unroll
        for (int i = 0; i < 2; i++) {
            int idx = tid + i * 256;
            int r   = idx >> 2;
            int kq  = (idx & 3) * 4;
            pa[i] = (brow + r < M)
                  ? *(const float4*)(A + (size_t)(brow + r) * lda + k0 + kq)
                  : make_float4(0.f, 0.f, 0.f, 0.f);
        }
        #pragma unroll
        for (int i = 0; i < B_ITERS; i++) {
            int idx = tid + i * 256;
            int k   = idx / F4_ROW;
            int n4  = (idx % F4_ROW) * 4;
            pb[i] = *(const float4*)(B + (size_t)(k0 + k) * ldb + bcol + n4);
        }
    };
    auto store_tile = [&](int s) {
        #pragma unroll
        for (int i = 0; i < 2; i++) {
            int idx = tid + i * 256;
            int r   = idx >> 2;
            int kq  = (idx & 3) * 4;
            float vv[4] = {pa[i].x, pa[i].y, pa[i].z, pa[i].w};
            unsigned short h[4], l[4];
            #pragma unroll
            for (int j = 0; j < 4; j++) split_bf16(vv[j], h[j], l[j]);
            int ci = (r * 2 + ((kq >> 3) ^ ((r >> 2) & 1))) * 8 + (kq & 4);
            *(uint2*)&Ah[s][ci] = make_uint2((unsigned)h[0] | ((unsigned)h[1] << 16),
                                             (unsigned)h[2] | ((unsigned)h[3] << 16));
            *(uint2*)&Al[s][ci] = make_uint2((unsigned)l[0] | ((unsigned)l[1] << 16),
                                             (unsigned)l[2] | ((unsigned)l[3] << 16));
        }
        #pragma unroll
        for (int i = 0; i < B_ITERS; i++) {
            int idx = tid + i * 256;
            int k   = idx / F4_ROW;
            int n4  = (idx % F4_ROW) * 4;
            float vv[4] = {pb[i].x, pb[i].y, pb[i].z, pb[i].w};
            unsigned short h[4], l[4];
            #pragma unroll
            for (int j = 0; j < 4; j++) split_bf16(vv[j], h[j], l[j]);
            int ci = (k * NB8 + ((n4 >> 3) ^ (k & 7))) * 8 + (n4 & 4);
            *(uint2*)&Bh[s][ci] = make_uint2((unsigned)h[0] | ((unsigned)h[1] << 16),
                                             (unsigned)h[2] | ((unsigned)h[3] << 16));
            *(uint2*)&Bl[s][ci] = make_uint2((unsigned)l[0] | ((unsigned)l[1] << 16),
                                             (unsigned)l[2] | ((unsigned)l[3] << 16));
        }
    };

    const int nk = K / 16;
    load_tile(0);
    store_tile(0);
    __syncthreads();

    for (int it = 0; it < nk; it++) {
        if (it + 1 < nk) load_tile((it + 1) * 16);

        const int cur = it & 1;
        unsigned bhf[4][2], blf[4][2];
        #pragma unroll
        for (int j = 0; j < 2; j++) {
            int k  = lane & 15;
            int n8 = ((warpN + j * 16) >> 3) + (lane >> 4);
            int ch = k * NB8 + (n8 ^ (k & 7));
            unsigned r4[4];
            ldsm4t(r4, &Bh[cur][ch * 8]);
            bhf[2 * j][0] = r4[0]; bhf[2 * j][1] = r4[1];
            bhf[2 * j + 1][0] = r4[2]; bhf[2 * j + 1][1] = r4[3];
            ldsm4t(r4, &Bl[cur][ch * 8]);
            blf[2 * j][0] = r4[0]; blf[2 * j][1] = r4[1];
            blf[2 * j + 1][0] = r4[2]; blf[2 * j + 1][1] = r4[3];
        }
        #pragma unroll
        for (int mt = 0; mt < MT; mt++) {
            int r  = warpM + mt * 16 + (lane & 15);
            int kh = lane >> 4;
            int ch = r * 2 + (kh ^ ((r >> 2) & 1));
            unsigned ah[4], al[4];
            ldsm4(ah, &Ah[cur][ch * 8]);
            ldsm4(al, &Al[cur][ch * 8]);
            #pragma unroll
            for (int nt = 0; nt < 4; nt++) {
                mma_bf16(acc[mt][nt], ah, bhf[nt]);
                mma_bf16(acc[mt][nt], ah, blf[nt]);
                mma_bf16(acc[mt][nt], al, bhf[nt]);
            }
        }
        // write NEXT tile into the other buffer; one sync covers both hazards
        if (it + 1 < nk) store_tile((it + 1) & 1);
        __syncthreads();
    }

    #pragma unroll
    for (int nt = 0; nt < 4; nt++) {
        int gc = bcol + warpN + nt * 8 + 2 * q;
        float bx = bias[gc], by = bias[gc + 1];
        #pragma unroll
        for (int mt = 0; mt < MT; mt++) {
            int gr0 = brow + warpM + mt * 16 + g;
            float v0 = acc[mt][nt][0] + bx;
            float v1 = acc[mt][nt][1] + by;
            float v2 = acc[mt][nt][2] + bx;
            float v3 = acc[mt][nt][3] + by;
            if (LEAKY) {
                v0 = (v0 > 0.f) ? v0 : SLOPE * v0;
                v1 = (v1 > 0.f) ? v1 : SLOPE * v1;
                v2 = (v2 > 0.f) ? v2 : SLOPE * v2;
                v3 = (v3 > 0.f) ? v3 : SLOPE * v3;
            }
            if (gr0 < M)     *(float2*)(C + (size_t)gr0 * ldc + gc)       = make_float2(v0, v1);
            if (gr0 + 8 < M) *(float2*)(C + (size_t)(gr0 + 8) * ldc + gc) = make_float2(v2, v3);
        }
    }
}

// ---------------- launcher ----------------
extern "C" void kernel_launch(void* const* d_in, const int* in_sizes, int n_in,
                              void* d_out, int out_size) {
    const float* x      = (const float*)d_in[0];
    const void*  ei     = d_in[1];
    const float* ea     = (const float*)d_in[2];
    const float* in_W   = (const float*)d_in[3];
    const float* in_b   = (const float*)d_in[4];
    const float* eW     = (const float*)d_in[5];
    const float* eB     = (const float*)d_in[6];
    const float* W1     = (const float*)d_in[7];
    const float* b1     = (const float*)d_in[8];
    const float* ln_g   = (const float*)d_in[9];
    const float* ln_b   = (const float*)d_in[10];
    const float* W2     = (const float*)d_in[11];
    const float* b2     = (const float*)d_in[12];
    const float* W3     = (const float*)d_in[13];
    const float* b3     = (const float*)d_in[14];
    const float* out_W  = (const float*)d_in[15];
    const float* out_b  = (const float*)d_in[16];
    float* out = (float*)d_out;

    float* HID; cudaGetSymbolAddress((void**)&HID, g_HID);
    float* Z;   cudaGetSymbolAddress((void**)&Z,   g_Z);
    float* T1;  cudaGetSymbolAddress((void**)&T1,  g_T1);
    float* T2;  cudaGetSymbolAddress((void**)&T2,  g_T2);

    // 0) dtype detect + zero + bucket scatter
    detect_zero_kernel<<<(NN + 1023) / 1024, 1024>>>((const unsigned int*)ei);
    scatter_kernel<<<(EE + 255) / 256, 256>>>(ei, ea);

    // 1) h0 = x @ in_W + in_b  -> HID[:, 0:128]
    bf16x3_gemm_kernel<64, false><<<dim3(79, 2), 256>>>(
        NN, 128, x, D_IN, in_W, HH, in_b, HID, 512);

    // 2) GINE layers
    for (int l = 0; l < LL; l++) {
        int hid_off = l * HH;
        const float* eWl = eW + l * D_CAT;
        const float* eBl = eB + l * D_CAT;
        const float* W1l = W1 + (size_t)l * D_CAT * WH;
        const float* W2l = W2 + (size_t)l * WH * WH;
        const float* W3l = W3 + (size_t)l * WH * HH;

        agg_z_kernel<<<(NN + 3) / 4, 256>>>(x, eWl, eBl, hid_off);
        bf16x3_gemm_kernel<128, false><<<dim3(79, 2), 256>>>(
            NN, D_CAT, Z, D_CAT, W1l, WH, b1 + l * WH, T1, WH);
        ln_leaky_kernel<<<NN / 8, 256>>>(T1, ln_g + l * WH, ln_b + l * WH);
        bf16x3_gemm_kernel<128, true><<<dim3(79, 2), 256>>>(
            NN, WH, T1, WH, W2l, WH, b2 + l * WH, T2, WH);
        bf16x3_gemm_kernel<64, false><<<dim3(79, 2), 256>>>(
            NN, WH, T2, WH, W3l, HH, b3 + l * HH, HID + (l + 1) * HH, 512);
    }

    // 3) out = HID @ out_W + out_b
    bf16x3_gemm_kernel<64, false><<<dim3(79, 2), 256>>>(
        NN, 512, HID, 512, out_W, D_OUT, out_b, out, D_OUT);

    (void)in_sizes; (void)n_in; (void)out_size;
}

// round 17
// speedup vs baseline: 1.0964x; 1.0392x over previous
#include <cuda_runtime.h>
#include <cuda_bf16.h>
#include <cstdint>

// ---------------- problem constants ----------------
#define NN      10000
#define EE      320000
#define D_IN    128
#define HH      128
#define LL      3
#define D_CAT   256
#define WH      256
#define D_OUT   128
#define LN_EPS  1e-5f
#define SLOPE   0.1f
#define CAP     128      // per-node edge bucket capacity (max degree ~65 for Poisson(32))

// ---------------- scratch ----------------
__device__ float g_HID[NN * 512];
__device__ float g_Z  [NN * D_CAT];
__device__ float g_T1 [NN * WH];
__device__ float g_T2 [NN * WH];
__device__ int   g_is_i64;
__device__ int   g_count[NN];
__device__ int2  g_srcea[NN * CAP];   // bucketed (src, ea bits) per dst

// ---------------- detect dtype + zero counters (merged) ----------------
__global__ void detect_zero_kernel(const unsigned int* __restrict__ w) {
    int i = blockIdx.x * blockDim.x + threadIdx.x;
    if (i < NN) g_count[i] = 0;
    if (blockIdx.x == 0) {
        __shared__ int bad;
        if (threadIdx.x == 0) bad = 0;
        __syncthreads();
        if (w[2 * threadIdx.x + 1] != 0u) atomicExch(&bad, 1);
        __syncthreads();
        if (threadIdx.x == 0) g_is_i64 = (bad == 0) ? 1 : 0;
    }
}

// ---------------- bucket scatter ----------------
__global__ void scatter_kernel(const void* __restrict__ ei,
                               const float* __restrict__ ea) {
    int e = blockIdx.x * blockDim.x + threadIdx.x;
    if (e >= EE) return;
    int src, dst;
    if (g_is_i64) {
        src = (int)((const long long*)ei)[e];
        dst = (int)((const long long*)ei)[EE + e];
    } else {
        src = ((const int*)ei)[e];
        dst = ((const int*)ei)[EE + e];
    }
    int pos = atomicAdd(&g_count[dst], 1);
    if (pos < CAP) g_srcea[dst * CAP + pos] = make_int2(src, __float_as_int(__ldg(ea + e)));
}

// ---------------- aggregation (R14 champion: fp32 gathers, 4 nodes/block) ----------------
__global__ void agg_z_kernel(const float* __restrict__ x,
                             const float* __restrict__ eWl,
                             const float* __restrict__ eBl,
                             int hid_off) {
    int node = blockIdx.x * 4 + (threadIdx.x >> 6);
    if (node >= NN) return;
    int lane = threadIdx.x & 63;
    int d = lane * 4;

    float4 w  = *(const float4*)(eWl + d);
    float4 bb = *(const float4*)(eBl + d);

    float4 acc;
    if (d < 128) acc = *(const float4*)(x + (size_t)node * D_IN + d);
    else         acc = *(const float4*)(g_HID + (size_t)node * 512 + hid_off + (d - 128));

    const float* gbase = (d < 128) ? (x + d) : (g_HID + hid_off + (d - 128));
    const size_t gstr  = (d < 128) ? D_IN : 512;

    int i   = node * CAP;
    int end = i + min(g_count[node], CAP);

    auto body = [&](int2 se) {
        float4 v = *(const float4*)(gbase + (size_t)se.x * gstr);
        float a = __int_as_float(se.y);
        acc.x += fmaxf(v.x + fmaf(a, w.x, bb.x), 0.f);
        acc.y += fmaxf(v.y + fmaf(a, w.y, bb.y), 0.f);
        acc.z += fmaxf(v.z + fmaf(a, w.z, bb.z), 0.f);
        acc.w += fmaxf(v.w + fmaf(a, w.w, bb.w), 0.f);
    };
    for (; i + 4 <= end; i += 4) {
        int2 s0 = g_srcea[i], s1 = g_srcea[i + 1], s2 = g_srcea[i + 2], s3 = g_srcea[i + 3];
        body(s0); body(s1); body(s2); body(s3);
    }
    for (; i < end; i++) body(g_srcea[i]);

    *(float4*)(g_Z + (size_t)node * D_CAT + d) = acc;
}

// ---------------- shared GEMM primitives ----------------
__device__ __forceinline__ void ldsm4(unsigned* r, const __nv_bfloat16* p) {
    unsigned a = (unsigned)__cvta_generic_to_shared(p);
    asm volatile("ldmatrix.sync.aligned.m8n8.x4.shared.b16 {%0,%1,%2,%3}, [%4];"
                 : "=r"(r[0]), "=r"(r[1]), "=r"(r[2]), "=r"(r[3]) : "r"(a));
}
__device__ __forceinline__ void ldsm4t(unsigned* r, const __nv_bfloat16* p) {
    unsigned a = (unsigned)__cvta_generic_to_shared(p);
    asm volatile("ldmatrix.sync.aligned.m8n8.x4.trans.shared.b16 {%0,%1,%2,%3}, [%4];"
                 : "=r"(r[0]), "=r"(r[1]), "=r"(r[2]), "=r"(r[3]) : "r"(a));
}
__device__ __forceinline__ void mma_bf16(float* c, const unsigned* a, const unsigned* b) {
    asm volatile("mma.sync.aligned.m16n8k16.row.col.f32.bf16.bf16.f32 "
                 "{%0,%1,%2,%3}, {%4,%5,%6,%7}, {%8,%9}, {%0,%1,%2,%3};"
                 : "+f"(c[0]), "+f"(c[1]), "+f"(c[2]), "+f"(c[3])
                 : "r"(a[0]), "r"(a[1]), "r"(a[2]), "r"(a[3]), "r"(b[0]), "r"(b[1]));
}
__device__ __forceinline__ void split_bf16(float v, unsigned short& h, unsigned short& l) {
    __nv_bfloat16 hb = __float2bfloat16_rn(v);
    float res = v - __bfloat162float(hb);
    h = __bfloat16_as_ushort(hb);
    l = __bfloat16_as_ushort(__float2bfloat16_rn(res));
}

// ================= bf16x3 tensor-core GEMM (R14 champion kernel, unchanged) =================
template <int BN, bool LEAKY>
__global__ __launch_bounds__(256, 2)
void bf16x3_gemm_kernel(int M, int K,
                        const float* __restrict__ A, int lda,
                        const float* __restrict__ B, int ldb,
                        const float* __restrict__ bias,
                        float* __restrict__ C, int ldc) {
    constexpr int NB8     = BN / 8;
    constexpr int WARPS_N = BN / 32;
    constexpr int WARPS_M = 8 / WARPS_N;
    constexpr int MT      = (128 / WARPS_M) / 16;
    constexpr int B_ITERS = BN / 64;
    constexpr int F4_ROW  = BN / 4;

    __shared__ __align__(16) __nv_bfloat16 Ah[128 * 16], Al[128 * 16];
    __shared__ __align__(16) __nv_bfloat16 Bh[16 * BN],  Bl[16 * BN];

    const int tid   = threadIdx.x;
    const int w     = tid >> 5;
    const int lane  = tid & 31;
    const int g     = lane >> 2;
    const int q     = lane & 3;
    const int warpN = (w % WARPS_N) * 32;
    const int warpM = (w / WARPS_N) * (MT * 16);
    const int brow  = blockIdx.x * 128;
    const int bcol  = blockIdx.y * BN;

    float acc[MT][4][4];
    #pragma unroll
    for (int mt = 0; mt < MT; mt++)
        #pragma unroll
        for (int nt = 0; nt < 4; nt++)
            #pragma unroll
            for (int i = 0; i < 4; i++) acc[mt][nt][i] = 0.f;

    float4 pa[2], pb[B_ITERS];

    auto load_tile = [&](int k0) {
        #pragma unroll
        for (int i = 0; i < 2; i++) {
            int idx = tid + i * 256;
            int r   = idx >> 2;
            int kq  = (idx & 3) * 4;
            pa[i] = (brow + r < M)
                  ? *(const float4*)(A + (size_t)(brow + r) * lda + k0 + kq)
                  : make_float4(0.f, 0.f, 0.f, 0.f);
        }
        #pragma unroll
        for (int i = 0; i < B_ITERS; i++) {
            int idx = tid + i * 256;
            int k   = idx / F4_ROW;
            int n4  = (idx % F4_ROW) * 4;
            pb[i] = *(const float4*)(B + (size_t)(k0 + k) * ldb + bcol + n4);
        }
    };
    auto store_tile = [&]() {
        #pragma unroll
        for (int i = 0; i < 2; i++) {
            int idx = tid + i * 256;
            int r   = idx >> 2;
            int kq  = (idx & 3) * 4;
            float vv[4] = {pa[i].x, pa[i].y, pa[i].z, pa[i].w};
            unsigned short h[4], l[4];
            #pragma unroll
            for (int j = 0; j < 4; j++) split_bf16(vv[j], h[j], l[j]);
            int ci = (r * 2 + ((kq >> 3) ^ ((r >> 2) & 1))) * 8 + (kq & 4);
            *(uint2*)&Ah[ci] = make_uint2((unsigned)h[0] | ((unsigned)h[1] << 16),
                                          (unsigned)h[2] | ((unsigned)h[3] << 16));
            *(uint2*)&Al[ci] = make_uint2((unsigned)l[0] | ((unsigned)l[1] << 16),
                                          (unsigned)l[2] | ((unsigned)l[3] << 16));
        }
        #pragma unroll
        for (int i = 0; i < B_ITERS; i++) {
            int idx = tid + i * 256;
            int k   = idx / F4_ROW;
            int n4  = (idx % F4_ROW) * 4;
            float vv[4] = {pb[i].x, pb[i].y, pb[i].z, pb[i].w};
            unsigned short h[4], l[4];
            #pragma unroll
            for (int j = 0; j < 4; j++) split_bf16(vv[j], h[j], l[j]);
            int ci = (k * NB8 + ((n4 >> 3) ^ (k & 7))) * 8 + (n4 & 4);
            *(uint2*)&Bh[ci] = make_uint2((unsigned)h[0] | ((unsigned)h[1] << 16),
                                          (unsigned)h[2] | ((unsigned)h[3] << 16));
            *(uint2*)&Bl[ci] = make_uint2((unsigned)l[0] | ((unsigned)l[1] << 16),
                                          (unsigned)l[2] | ((unsigned)l[3] << 16));
        }
    };

    load_tile(0);
    store_tile();
    __syncthreads();

    for (int k0 = 0; k0 < K; k0 += 16) {
        bool more = (k0 + 16) < K;
        if (more) load_tile(k0 + 16);

        unsigned bhf[4][2], blf[4][2];
        #pragma unroll
        for (int j = 0; j < 2; j++) {
            int k  = lane & 15;
            int n8 = ((warpN + j * 16) >> 3) + (lane >> 4);
            int ch = k * NB8 + (n8 ^ (k & 7));
            unsigned r4[4];
            ldsm4t(r4, &Bh[ch * 8]);
            bhf[2 * j][0] = r4[0]; bhf[2 * j][1] = r4[1];
            bhf[2 * j + 1][0] = r4[2]; bhf[2 * j + 1][1] = r4[3];
            ldsm4t(r4, &Bl[ch * 8]);
            blf[2 * j][0] = r4[0]; blf[2 * j][1] = r4[1];
            blf[2 * j + 1][0] = r4[2]; blf[2 * j + 1][1] = r4[3];
        }
        #pragma unroll
        for (int mt = 0; mt < MT; mt++) {
            int r  = warpM + mt * 16 + (lane & 15);
            int kh = lane >> 4;
            int ch = r * 2 + (kh ^ ((r >> 2) & 1));
            unsigned ah[4], al[4];
            ldsm4(ah, &Ah[ch * 8]);
            ldsm4(al, &Al[ch * 8]);
            #pragma unroll
            for (int nt = 0; nt < 4; nt++) {
                mma_bf16(acc[mt][nt], ah, bhf[nt]);
                mma_bf16(acc[mt][nt], ah, blf[nt]);
                mma_bf16(acc[mt][nt], al, bhf[nt]);
            }
        }
        __syncthreads();
        if (more) {
            store_tile();
            __syncthreads();
        }
    }

    #pragma unroll
    for (int nt = 0; nt < 4; nt++) {
        int gc = bcol + warpN + nt * 8 + 2 * q;
        float bx = bias[gc], by = bias[gc + 1];
        #pragma unroll
        for (int mt = 0; mt < MT; mt++) {
            int gr0 = brow + warpM + mt * 16 + g;
            float v0 = acc[mt][nt][0] + bx;
            float v1 = acc[mt][nt][1] + by;
            float v2 = acc[mt][nt][2] + bx;
            float v3 = acc[mt][nt][3] + by;
            if (LEAKY) {
                v0 = (v0 > 0.f) ? v0 : SLOPE * v0;
                v1 = (v1 > 0.f) ? v1 : SLOPE * v1;
                v2 = (v2 > 0.f) ? v2 : SLOPE * v2;
                v3 = (v3 > 0.f) ? v3 : SLOPE * v3;
            }
            if (gr0 < M)     *(float2*)(C + (size_t)gr0 * ldc + gc)       = make_float2(v0, v1);
            if (gr0 + 8 < M) *(float2*)(C + (size_t)(gr0 + 8) * ldc + gc) = make_float2(v2, v3);
        }
    }
}

// ================= fused W1-GEMM + LayerNorm + LeakyReLU =================
// BM=64, BN=256 (full row per CTA), BK=16, 8 warps (each warp: 64 rows x 32 cols).
// C = leaky(LN(A@B + bias) * lng + lnb), A:[M,256], B:[256,256].
__global__ __launch_bounds__(256, 2)
void w1_ln_gemm_kernel(int M,
                       const float* __restrict__ A,
                       const float* __restrict__ B,
                       const float* __restrict__ bias,
                       const float* __restrict__ lng,
                       const float* __restrict__ lnb,
                       float* __restrict__ C) {
    constexpr int K = 256, BN = 256, NB8 = BN / 8;

    __shared__ __align__(16) __nv_bfloat16 Ah[64 * 16], Al[64 * 16];
    __shared__ __align__(16) __nv_bfloat16 Bh[16 * BN], Bl[16 * BN];
    __shared__ float sS[64 * 8], sQ[64 * 8];
    __shared__ float sMu[64], sRstd[64];

    const int tid   = threadIdx.x;
    const int w     = tid >> 5;
    const int lane  = tid & 31;
    const int g     = lane >> 2;
    const int q     = lane & 3;
    const int warpN = w * 32;
    const int brow  = blockIdx.x * 64;

    float acc[4][4][4];
    #pragma unroll
    for (int mt = 0; mt < 4; mt++)
        #pragma unroll
        for (int nt = 0; nt < 4; nt++)
            #pragma unroll
            for (int i = 0; i < 4; i++) acc[mt][nt][i] = 0.f;

    float4 pa, pb[4];

    auto load_tile = [&](int k0) {
        {
            int r  = tid >> 2;
            int kq = (tid & 3) * 4;
            pa = (brow + r < M)
               ? *(const float4*)(A + (size_t)(brow + r) * K + k0 + kq)
               : make_float4(0.f, 0.f, 0.f, 0.f);
        }
        #pragma unroll
        for (int i = 0; i < 4; i++) {
            int idx = tid + i * 256;
            int k   = idx >> 6;
            int n4  = (idx & 63) * 4;
            pb[i] = *(const float4*)(B + (size_t)(k0 + k) * BN + n4);
        }
    };
    auto store_tile = [&]() {
        {
            int r  = tid >> 2;
            int kq = (tid & 3) * 4;
            float vv[4] = {pa.x, pa.y, pa.z, pa.w};
            unsigned short h[4], l[4];
            #pragma unroll
            for (int j = 0; j < 4; j++) split_bf16(vv[j], h[j], l[j]);
            int ci = (r * 2 + ((kq >> 3) ^ ((r >> 2) & 1))) * 8 + (kq & 4);
            *(uint2*)&Ah[ci] = make_uint2((unsigned)h[0] | ((unsigned)h[1] << 16),
                                          (unsigned)h[2] | ((unsigned)h[3] << 16));
            *(uint2*)&Al[ci] = make_uint2((unsigned)l[0] | ((unsigned)l[1] << 16),
                                          (unsigned)l[2] | ((unsigned)l[3] << 16));
        }
        #pragma unroll
        for (int i = 0; i < 4; i++) {
            int idx = tid + i * 256;
            int k   = idx >> 6;
            int n4  = (idx & 63) * 4;
            float vv[4] = {pb[i].x, pb[i].y, pb[i].z, pb[i].w};
            unsigned short h[4], l[4];
            #pragma unroll
            for (int j = 0; j < 4; j++) split_bf16(vv[j], h[j], l[j]);
            int ci = (k * NB8 + ((n4 >> 3) ^ (k & 7))) * 8 + (n4 & 4);
            *(uint2*)&Bh[ci] = make_uint2((unsigned)h[0] | ((unsigned)h[1] << 16),
                                          (unsigned)h[2] | ((unsigned)h[3] << 16));
            *(uint2*)&Bl[ci] = make_uint2((unsigned)l[0] | ((unsigned)l[1] << 16),
                                          (unsigned)l[2] | ((unsigned)l[3] << 16));
        }
    };

    load_tile(0);
    store_tile();
    __syncthreads();

    for (int k0 = 0; k0 < K; k0 += 16) {
        bool more = (k0 + 16) < K;
        if (more) load_tile(k0 + 16);

        unsigned bhf[4][2], blf[4][2];
        #pragma unroll
        for (int j = 0; j < 2; j++) {
            int k  = lane & 15;
            int n8 = ((warpN + j * 16) >> 3) + (lane >> 4);
            int ch = k * NB8 + (n8 ^ (k & 7));
            unsigned r4[4];
            ldsm4t(r4, &Bh[ch * 8]);
            bhf[2 * j][0] = r4[0]; bhf[2 * j][1] = r4[1];
            bhf[2 * j + 1][0] = r4[2]; bhf[2 * j + 1][1] = r4[3];
            ldsm4t(r4, &Bl[ch * 8]);
            blf[2 * j][0] = r4[0]; blf[2 * j][1] = r4[1];
            blf[2 * j + 1][0] = r4[2]; blf[2 * j + 1][1] = r4[3];
        }
        #pragma unroll
        for (int mt = 0; mt < 4; mt++) {
            int r  = mt * 16 + (lane & 15);
            int kh = lane >> 4;
            int ch = r * 2 + (kh ^ ((r >> 2) & 1));
            unsigned ah[4], al[4];
            ldsm4(ah, &Ah[ch * 8]);
            ldsm4(al, &Al[ch * 8]);
            #pragma unroll
            for (int nt = 0; nt < 4; nt++) {
                mma_bf16(acc[mt][nt], ah, bhf[nt]);
                mma_bf16(acc[mt][nt], ah, blf[nt]);
                mma_bf16(acc[mt][nt], al, bhf[nt]);
            }
        }
        __syncthreads();
        if (more) {
            store_tile();
            __syncthreads();
        }
    }

    // ---- epilogue: add bias, LN stats, apply LN+leaky, store ----
    #pragma unroll
    for (int nt = 0; nt < 4; nt++) {
        int gc = warpN + nt * 8 + 2 * q;
        float bx = bias[gc], by = bias[gc + 1];
        #pragma unroll
        for (int mt = 0; mt < 4; mt++) {
            acc[mt][nt][0] += bx; acc[mt][nt][1] += by;
            acc[mt][nt][2] += bx; acc[mt][nt][3] += by;
        }
    }
    // per-row partials: row rA = mt*16+g (i=0,1), rB = rA+8 (i=2,3)
    #pragma unroll
    for (int mt = 0; mt < 4; mt++) {
        float s0 = 0.f, q0 = 0.f, s1 = 0.f, q1 = 0.f;
        #pragma unroll
        for (int nt = 0; nt < 4; nt++) {
            float a0 = acc[mt][nt][0], a1 = acc[mt][nt][1];
            float a2 = acc[mt][nt][2], a3 = acc[mt][nt][3];
            s0 += a0 + a1; q0 += a0 * a0 + a1 * a1;
            s1 += a2 + a3; q1 += a2 * a2 + a3 * a3;
        }
        #pragma unroll
        for (int off = 1; off < 4; off <<= 1) {
            s0 += __shfl_xor_sync(0xffffffffu, s0, off);
            q0 += __shfl_xor_sync(0xffffffffu, q0, off);
            s1 += __shfl_xor_sync(0xffffffffu, s1, off);
            q1 += __shfl_xor_sync(0xffffffffu, q1, off);
        }
        if (q == 0) {
            int rA = mt * 16 + g, rB = rA + 8;
            sS[rA * 8 + w] = s0; sQ[rA * 8 + w] = q0;
            sS[rB * 8 + w] = s1; sQ[rB * 8 + w] = q1;
        }
    }
    __syncthreads();
    if (tid < 64) {
        float s = 0.f, qq = 0.f;
        #pragma unroll
        for (int j = 0; j < 8; j++) { s += sS[tid * 8 + j]; qq += sQ[tid * 8 + j]; }
        float mu  = s * (1.0f / WH);
        float var = qq * (1.0f / WH) - mu * mu;
        sMu[tid]   = mu;
        sRstd[tid] = rsqrtf(var + LN_EPS);
    }
    __syncthreads();

    #pragma unroll
    for (int nt = 0; nt < 4; nt++) {
        int gc = warpN + nt * 8 + 2 * q;
        float gx = __ldg(lng + gc), gy = __ldg(lng + gc + 1);
        float ox = __ldg(lnb + gc), oy = __ldg(lnb + gc + 1);
        #pragma unroll
        for (int mt = 0; mt < 4; mt++) {
            int rA = mt * 16 + g;
            int rB = rA + 8;
            float muA = sMu[rA], rsA = sRstd[rA];
            float muB = sMu[rB], rsB = sRstd[rB];
            float y0 = (acc[mt][nt][0] - muA) * rsA * gx + ox;
            float y1 = (acc[mt][nt][1] - muA) * rsA * gy + oy;
            float y2 = (acc[mt][nt][2] - muB) * rsB * gx + ox;
            float y3 = (acc[mt][nt][3] - muB) * rsB * gy + oy;
            y0 = (y0 > 0.f) ? y0 : SLOPE * y0;
            y1 = (y1 > 0.f) ? y1 : SLOPE * y1;
            y2 = (y2 > 0.f) ? y2 : SLOPE * y2;
            y3 = (y3 > 0.f) ? y3 : SLOPE * y3;
            int grA = brow + rA;
            if (grA < M)     *(float2*)(C + (size_t)grA * WH + gc)       = make_float2(y0, y1);
            if (grA + 8 < M) *(float2*)(C + (size_t)(grA + 8) * WH + gc) = make_float2(y2, y3);
        }
    }
}

// ---------------- launcher ----------------
extern "C" void kernel_launch(void* const* d_in, const int* in_sizes, int n_in,
                              void* d_out, int out_size) {
    const float* x      = (const float*)d_in[0];
    const void*  ei     = d_in[1];
    const float* ea     = (const float*)d_in[2];
    const float* in_W   = (const float*)d_in[3];
    const float* in_b   = (const float*)d_in[4];
    const float* eW     = (const float*)d_in[5];
    const float* eB     = (const float*)d_in[6];
    const float* W1     = (const float*)d_in[7];
    const float* b1     = (const float*)d_in[8];
    const float* ln_g   = (const float*)d_in[9];
    const float* ln_b   = (const float*)d_in[10];
    const float* W2     = (const float*)d_in[11];
    const float* b2     = (const float*)d_in[12];
    const float* W3     = (const float*)d_in[13];
    const float* b3     = (const float*)d_in[14];
    const float* out_W  = (const float*)d_in[15];
    const float* out_b  = (const float*)d_in[16];
    float* out = (float*)d_out;

    float* HID; cudaGetSymbolAddress((void**)&HID, g_HID);
    float* Z;   cudaGetSymbolAddress((void**)&Z,   g_Z);
    float* T1;  cudaGetSymbolAddress((void**)&T1,  g_T1);
    float* T2;  cudaGetSymbolAddress((void**)&T2,  g_T2);

    // 0) dtype detect + zero + bucket scatter
    detect_zero_kernel<<<(NN + 1023) / 1024, 1024>>>((const unsigned int*)ei);
    scatter_kernel<<<(EE + 255) / 256, 256>>>(ei, ea);

    // 1) h0 = x @ in_W + in_b  -> HID[:, 0:128]
    bf16x3_gemm_kernel<64, false><<<dim3(79, 2), 256>>>(
        NN, 128, x, D_IN, in_W, HH, in_b, HID, 512);

    // 2) GINE layers
    for (int l = 0; l < LL; l++) {
        int hid_off = l * HH;
        const float* eWl = eW + l * D_CAT;
        const float* eBl = eB + l * D_CAT;
        const float* W1l = W1 + (size_t)l * D_CAT * WH;
        const float* W2l = W2 + (size_t)l * WH * WH;
        const float* W3l = W3 + (size_t)l * WH * HH;

        agg_z_kernel<<<(NN + 3) / 4, 256>>>(x, eWl, eBl, hid_off);
        // T1 = leaky(LN(Z @ W1 + b1))  — fused GEMM+LN
        w1_ln_gemm_kernel<<<157, 256>>>(
            NN, Z, W1l, b1 + l * WH, ln_g + l * WH, ln_b + l * WH, T1);
        bf16x3_gemm_kernel<128, true><<<dim3(79, 2), 256>>>(
            NN, WH, T1, WH, W2l, WH, b2 + l * WH, T2, WH);
        bf16x3_gemm_kernel<64, false><<<dim3(79, 2), 256>>>(
            NN, WH, T2, WH, W3l, HH, b3 + l * HH, HID + (l + 1) * HH, 512);
    }

    // 3) out = HID @ out_W + out_b
    bf16x3_gemm_kernel<64, false><<<dim3(79, 2), 256>>>(
        NN, 512, HID, 512, out_W, D_OUT, out_b, out, D_OUT);

    (void)in_sizes; (void)n_in; (void)out_size;
}